// round 1
// baseline (speedup 1.0000x reference)
#include <cuda_runtime.h>
#include <cstdint>
#include <cstddef>

// ExpertGather: out[b,e,k,j] = sum_i x[b, Ind[b,e,k], i] * W[e,i,j]
// B=8, T=8192, I=512, E=16, K=1024, J=512  (all fp32)
//
// Strategy: 128 independent 1024x512x512 GEMMs (one per (b,e)), gather fused
// into the A-tile smem load. TF32 mma.sync (m16n8k8) with fp32 accumulate for
// precision safety (expected rel_err ~5e-4 < 1e-3).
// CTA tile 128x128, K-tile 32. 8 warps in 2x4 grid, each warp 64x32.

namespace {

constexpr int Bdim = 8;
constexpr int Tdim = 8192;
constexpr int Idim = 512;   // reduction dim
constexpr int Edim = 16;
constexpr int Ktok = 1024;  // tokens per expert
constexpr int Jdim = 512;   // output features

constexpr int BM = 128;
constexpr int BN = 128;
constexpr int BK = 32;
constexpr int SSTR = 132;   // padded smem stride (128 + 4) -> <=2-way LDS conflicts

__device__ __forceinline__ uint32_t f2tf(float f) {
    uint32_t u;
    asm("cvt.rna.tf32.f32 %0, %1;" : "=r"(u) : "f"(f));
    return u;
}

}  // namespace

__global__ __launch_bounds__(256, 1) void expert_gather_gemm(
    const float* __restrict__ x,     // [B, T, I]
    const int*   __restrict__ Ind,   // [B, E, K]
    const float* __restrict__ W,     // [E, I, J]
    float*       __restrict__ out)   // [B, E, K, J]
{
    __shared__ float A_s[BK][SSTR];  // [k][m]  (transposed for mma lds)
    __shared__ float B_s[BK][SSTR];  // [k][n]

    const int be = blockIdx.z;              // b*E + e
    const int b  = be >> 4;
    const int e  = be & 15;
    const int m0 = blockIdx.y * BM;
    const int n0 = blockIdx.x * BN;

    const int t    = threadIdx.x;
    const int lane = t & 31;
    const int warp = t >> 5;
    const int grp  = lane >> 2;   // 0..7
    const int tig  = lane & 3;    // 0..3
    const int warp_m = warp >> 2; // 0..1  (64 rows each)
    const int warp_n = warp & 3;  // 0..3  (32 cols each)

    // ---- A (gather) load assignment: thread owns one tile-row, 4 float4 chunks
    const int am  = t & 127;                       // m within tile
    const int ac0 = t >> 7;                        // 0 or 1 -> chunks {ac0, ac0+2, ac0+4, ac0+6}
    const int rowtok = Ind[be * Ktok + m0 + am];   // gathered token index
    const float* xrow = x + ((size_t)b * Tdim + rowtok) * Idim;

    // ---- B load assignment: 32x128 tile = 1024 float4, 4 per thread
    const int bn4 = t & 31;   // float4 column
    const int bk0 = t >> 5;   // 0..7
    const float* wb = W + (size_t)e * Idim * Jdim + n0;

    float acc[4][4][4];
    #pragma unroll
    for (int i = 0; i < 4; i++)
        #pragma unroll
        for (int j = 0; j < 4; j++)
            #pragma unroll
            for (int q = 0; q < 4; q++) acc[i][j][q] = 0.0f;

    for (int k0 = 0; k0 < Idim; k0 += BK) {
        // Gathered A tile: x[b, rowtok, k0 : k0+32] -> A_s[k][m] (transposed store)
        #pragma unroll
        for (int i = 0; i < 4; i++) {
            const int c4 = ac0 + 2 * i;  // float4 chunk 0..7 within the 32-wide K tile
            const float4 v = *reinterpret_cast<const float4*>(xrow + k0 + c4 * 4);
            A_s[c4 * 4 + 0][am] = v.x;
            A_s[c4 * 4 + 1][am] = v.y;
            A_s[c4 * 4 + 2][am] = v.z;
            A_s[c4 * 4 + 3][am] = v.w;
        }
        // W tile: W[e, k0+k, n0 : n0+128] -> B_s[k][n]
        #pragma unroll
        for (int i = 0; i < 4; i++) {
            const int k = bk0 + 8 * i;
            const float4 v = *reinterpret_cast<const float4*>(
                wb + (size_t)(k0 + k) * Jdim + bn4 * 4);
            *reinterpret_cast<float4*>(&B_s[k][bn4 * 4]) = v;
        }
        __syncthreads();

        #pragma unroll
        for (int ks = 0; ks < BK / 8; ks++) {
            const int kb = ks * 8;
            // B fragments for this warp's 4 n-tiles of 8
            uint32_t bb[4][2];
            #pragma unroll
            for (int fn = 0; fn < 4; fn++) {
                const int n = warp_n * 32 + fn * 8 + grp;
                bb[fn][0] = f2tf(B_s[kb + tig][n]);
                bb[fn][1] = f2tf(B_s[kb + tig + 4][n]);
            }
            #pragma unroll
            for (int fm = 0; fm < 4; fm++) {
                const int m = warp_m * 64 + fm * 16 + grp;
                const uint32_t a0 = f2tf(A_s[kb + tig][m]);
                const uint32_t a1 = f2tf(A_s[kb + tig][m + 8]);
                const uint32_t a2 = f2tf(A_s[kb + tig + 4][m]);
                const uint32_t a3 = f2tf(A_s[kb + tig + 4][m + 8]);
                #pragma unroll
                for (int fn = 0; fn < 4; fn++) {
                    asm volatile(
                        "mma.sync.aligned.m16n8k8.row.col.f32.tf32.tf32.f32 "
                        "{%0,%1,%2,%3}, {%4,%5,%6,%7}, {%8,%9}, {%0,%1,%2,%3};\n"
                        : "+f"(acc[fm][fn][0]), "+f"(acc[fm][fn][1]),
                          "+f"(acc[fm][fn][2]), "+f"(acc[fm][fn][3])
                        : "r"(a0), "r"(a1), "r"(a2), "r"(a3),
                          "r"(bb[fn][0]), "r"(bb[fn][1]));
                }
            }
        }
        __syncthreads();
    }

    // Epilogue: c0/c1 = (row grp, cols 2tig,2tig+1), c2/c3 = row grp+8.
    float* ob = out + ((size_t)be * Ktok + m0) * (size_t)Jdim + n0;
    #pragma unroll
    for (int fm = 0; fm < 4; fm++) {
        #pragma unroll
        for (int fn = 0; fn < 4; fn++) {
            const int r0 = warp_m * 64 + fm * 16 + grp;
            const int cc = warp_n * 32 + fn * 8 + 2 * tig;
            const float2 v0 = make_float2(acc[fm][fn][0], acc[fm][fn][1]);
            const float2 v1 = make_float2(acc[fm][fn][2], acc[fm][fn][3]);
            *reinterpret_cast<float2*>(ob + (size_t)r0 * Jdim + cc)       = v0;
            *reinterpret_cast<float2*>(ob + (size_t)(r0 + 8) * Jdim + cc) = v1;
        }
    }
}

extern "C" void kernel_launch(void* const* d_in, const int* in_sizes, int n_in,
                              void* d_out, int out_size) {
    const float* x   = (const float*)d_in[0];
    const int*   Ind = (const int*)d_in[1];
    const float* W   = (const float*)d_in[2];
    float*       out = (float*)d_out;

    dim3 grid(Jdim / BN, Ktok / BM, Bdim * Edim);  // (4, 8, 128)
    expert_gather_gemm<<<grid, 256>>>(x, Ind, W, out);
}

// round 3
// speedup vs baseline: 1.9718x; 1.9718x over previous
#include <cuda_runtime.h>
#include <cstdint>
#include <cstddef>

// ExpertGather, sm_103 baseline ISA (no tcgen05 — target is sm_103, not sm_103a).
// out[b,e,k,j] = sum_i x[b, Ind[b,e,k], i] * W[e,i,j]
// B=8 T=8192 I=512 E=16 K=1024 J=512, fp32.
//
// tf32 mma.sync.m16n8k8, fragments loaded via ldmatrix.x4.b16 (tf32 fragment ==
// b16 16x16 ldmatrix), 3-stage cp.async pipeline, SW128-swizzled smem.
// A = gathered x rows [tok][k] (M=128), B = Wt rows [j][k] (N=256, W pre-
// transposed + pre-rounded to tf32). Warp tile 64x64 (8 warps).

namespace {
constexpr int Tdim = 8192;
constexpr int Idim = 512;
constexpr int Edim = 16;
constexpr int Ktok = 1024;
constexpr int Jdim = 512;

constexpr int BM = 128;            // tok tile (M)
constexpr int BN = 256;            // j tile (N)
constexpr int NKT = Idim / 32;     // 16 k-tiles of 32 floats (128B rows)
constexpr int NSTAGE = 3;

constexpr int A_BYTES = BM * 128;            // 16KB
constexpr int B_BYTES = BN * 128;            // 32KB
constexpr int STAGE_BYTES = A_BYTES + B_BYTES;  // 48KB
constexpr int SMEM_TOTAL = NSTAGE * STAGE_BYTES; // 147456

__device__ float g_Wt[(size_t)Edim * Jdim * Idim];  // Wt[e][j][i], tf32-rounded

__device__ __forceinline__ uint32_t smem_u32(const void* p) {
    uint32_t a;
    asm("{ .reg .u64 t; cvta.to.shared.u64 t, %1; cvt.u32.u64 %0, t; }" : "=r"(a) : "l"(p));
    return a;
}
__device__ __forceinline__ uint32_t f2tf(float f) {
    uint32_t u;
    asm("cvt.rna.tf32.f32 %0, %1;" : "=r"(u) : "f"(f));
    return u;
}
__device__ __forceinline__ uint32_t cvt_r(uint32_t v) {
    uint32_t u;
    asm("cvt.rna.tf32.f32 %0, %1;" : "=r"(u) : "r"(v));
    return u;
}
__device__ __forceinline__ void cp16(uint32_t dst, const void* src) {
    asm volatile("cp.async.cg.shared.global [%0], [%1], 16;" :: "r"(dst), "l"(src) : "memory");
}
__device__ __forceinline__ void cp_commit() {
    asm volatile("cp.async.commit_group;" ::: "memory");
}
__device__ __forceinline__ void cp_wait2() {
    asm volatile("cp.async.wait_group 2;" ::: "memory");
}
__device__ __forceinline__ void ldsm4(uint32_t* r, uint32_t addr) {
    asm volatile("ldmatrix.sync.aligned.m8n8.x4.shared.b16 {%0,%1,%2,%3}, [%4];"
                 : "=r"(r[0]), "=r"(r[1]), "=r"(r[2]), "=r"(r[3]) : "r"(addr));
}
__device__ __forceinline__ void mma8(float* c, uint32_t a0, uint32_t a1, uint32_t a2,
                                     uint32_t a3, uint32_t b0, uint32_t b1) {
    asm volatile(
        "mma.sync.aligned.m16n8k8.row.col.f32.tf32.tf32.f32 "
        "{%0,%1,%2,%3}, {%4,%5,%6,%7}, {%8,%9}, {%0,%1,%2,%3};\n"
        : "+f"(c[0]), "+f"(c[1]), "+f"(c[2]), "+f"(c[3])
        : "r"(a0), "r"(a1), "r"(a2), "r"(a3), "r"(b0), "r"(b1));
}
}  // namespace

// ---- W[e][i][j] -> Wt[e][j][i], rounded to tf32 ----
__global__ void transpose_w(const float* __restrict__ W) {
    __shared__ float tile[32][33];
    const int e = blockIdx.z;
    const int i0 = blockIdx.x * 32, j0 = blockIdx.y * 32;
    const float* Wp = W + (size_t)e * Idim * Jdim;
    float* Wtp = g_Wt + (size_t)e * Jdim * Idim;
    const int tx = threadIdx.x, ty = threadIdx.y;  // (32,8)
    #pragma unroll
    for (int r = 0; r < 32; r += 8)
        tile[ty + r][tx] = Wp[(size_t)(i0 + ty + r) * Jdim + j0 + tx];
    __syncthreads();
    #pragma unroll
    for (int r = 0; r < 32; r += 8)
        Wtp[(size_t)(j0 + ty + r) * Idim + i0 + tx] =
            __uint_as_float(f2tf(tile[tx][ty + r]));
}

// ---- fused gather + GEMM ----
extern __shared__ __align__(1024) unsigned char smem_raw[];

__global__ __launch_bounds__(256) void eg_mma(
    const float* __restrict__ x,     // [B, T, I]
    const int*   __restrict__ Ind,   // [B, E, K]
    float*       __restrict__ out)   // [B, E, K, J]
{
    const uint32_t sb = smem_u32(smem_raw);

    const int be   = blockIdx.z;
    const int b    = be >> 4;
    const int e    = be & 15;
    const int j0   = blockIdx.x * BN;
    const int tok0 = blockIdx.y * BM;

    const int t    = threadIdx.x;
    const int warp = t >> 5;
    const int lane = t & 31;
    const int warp_m = warp & 1;   // 2 x 64 tok
    const int warp_n = warp >> 1;  // 4 x 64 j
    const int grp = lane >> 2;
    const int tig = lane & 3;

    // ---- cp.async assignments (16B chunks; rows are 128B) ----
    const int ccol = t & 7;        // 16B col in row
    const int rb   = t >> 3;       // 0..31
    const uint32_t sw16 = (uint32_t)((ccol ^ (rb & 7)) << 4);
    const uint32_t dst_row = (uint32_t)rb * 128 + sw16;

    const float* asrc[4];
    #pragma unroll
    for (int i = 0; i < 4; ++i) {
        const int tok = Ind[(size_t)be * Ktok + tok0 + rb + 32 * i];
        asrc[i] = x + ((size_t)b * Tdim + tok) * Idim + ccol * 4;
    }
    const float* bsrc = g_Wt + ((size_t)e * Jdim + j0 + rb) * Idim + ccol * 4;

    // ---- ldmatrix per-lane address components ----
    const int l7 = lane & 7;
    const uint32_t a_lm = (uint32_t)(warp_m * 64 + ((lane >> 3) & 1) * 8 + l7) * 128;
    const uint32_t akc  = (uint32_t)(lane >> 4);        // 0/1
    const uint32_t b_lm = (uint32_t)(warp_n * 64 + ((lane >> 4) << 3) + l7) * 128;
    const uint32_t bkc  = (uint32_t)((lane >> 3) & 1);  // 0/1

    float acc[4][8][4];
    #pragma unroll
    for (int i = 0; i < 4; ++i)
        #pragma unroll
        for (int j = 0; j < 8; ++j)
            #pragma unroll
            for (int q = 0; q < 4; ++q) acc[i][j][q] = 0.0f;

    auto issue = [&](int s, int kt) {
        const uint32_t as = sb + (uint32_t)(s * STAGE_BYTES) + dst_row;
        #pragma unroll
        for (int i = 0; i < 4; ++i) cp16(as + i * 4096u, asrc[i] + kt * 32);
        const uint32_t bs = sb + (uint32_t)(s * STAGE_BYTES + A_BYTES) + dst_row;
        #pragma unroll
        for (int i = 0; i < 8; ++i) cp16(bs + i * 4096u, bsrc + kt * 32 + (size_t)i * 32 * Idim);
    };

    issue(0, 0); cp_commit();
    issue(1, 1); cp_commit();

    for (int kt = 0; kt < NKT; ++kt) {
        if (kt + 2 < NKT) issue((kt + 2) % NSTAGE, kt + 2);
        cp_commit();
        cp_wait2();
        __syncthreads();

        const int s = kt % NSTAGE;
        const uint32_t Abase = sb + (uint32_t)(s * STAGE_BYTES) + a_lm;
        const uint32_t Bbase = sb + (uint32_t)(s * STAGE_BYTES + A_BYTES) + b_lm;

        #pragma unroll
        for (int ks = 0; ks < 4; ++ks) {
            uint32_t af[4][4], bf[4][4];
            #pragma unroll
            for (int fm = 0; fm < 4; ++fm)
                ldsm4(af[fm], Abase + fm * 2048u + (((2u * ks + akc) ^ (uint32_t)l7) << 4));
            #pragma unroll
            for (int p = 0; p < 4; ++p)
                ldsm4(bf[p], Bbase + p * 2048u + (((2u * ks + bkc) ^ (uint32_t)l7) << 4));
            // tf32-round A fragments (x data); B (Wt) is pre-rounded.
            #pragma unroll
            for (int fm = 0; fm < 4; ++fm)
                #pragma unroll
                for (int q = 0; q < 4; ++q) af[fm][q] = cvt_r(af[fm][q]);
            #pragma unroll
            for (int fm = 0; fm < 4; ++fm)
                #pragma unroll
                for (int p = 0; p < 4; ++p) {
                    mma8(acc[fm][2 * p],     af[fm][0], af[fm][1], af[fm][2], af[fm][3],
                         bf[p][0], bf[p][1]);
                    mma8(acc[fm][2 * p + 1], af[fm][0], af[fm][1], af[fm][2], af[fm][3],
                         bf[p][2], bf[p][3]);
                }
        }
        __syncthreads();
    }

    // ---- epilogue ----
    float* ob = out + ((size_t)be * Ktok) * Jdim;
    #pragma unroll
    for (int fm = 0; fm < 4; ++fm) {
        const int r0 = tok0 + warp_m * 64 + fm * 16 + grp;
        #pragma unroll
        for (int fn = 0; fn < 8; ++fn) {
            const int cc = j0 + warp_n * 64 + fn * 8 + 2 * tig;
            *reinterpret_cast<float2*>(ob + (size_t)r0 * Jdim + cc) =
                make_float2(acc[fm][fn][0], acc[fm][fn][1]);
            *reinterpret_cast<float2*>(ob + (size_t)(r0 + 8) * Jdim + cc) =
                make_float2(acc[fm][fn][2], acc[fm][fn][3]);
        }
    }
}

extern "C" void kernel_launch(void* const* d_in, const int* in_sizes, int n_in,
                              void* d_out, int out_size) {
    const float* x   = (const float*)d_in[0];
    const int*   Ind = (const int*)d_in[1];
    const float* W   = (const float*)d_in[2];
    float*       out = (float*)d_out;

    static bool init_done = false;
    if (!init_done) {
        cudaFuncSetAttribute(eg_mma, cudaFuncAttributeMaxDynamicSharedMemorySize,
                             SMEM_TOTAL);
        init_done = true;
    }

    {
        dim3 g(Idim / 32, Jdim / 32, Edim), blk(32, 8);
        transpose_w<<<g, blk>>>(W);
    }
    {
        dim3 g(Jdim / BN, Ktok / BM, 8 * Edim);  // (2, 8, 128)
        eg_mma<<<g, 256, SMEM_TOTAL>>>(x, Ind, out);
    }
}

// round 5
// speedup vs baseline: 2.1580x; 1.0944x over previous
#include <cuda_runtime.h>
#include <cstdint>
#include <cstddef>

// ExpertGather, sm_103 baseline ISA. out[b,e,k,j] = sum_i x[b,Ind[b,e,k],i]*W[e,i,j]
// B=8 T=8192 I=512 E=16 K=1024 J=512, fp32.
//
// tf32 mma.sync.m16n8k8 + ldmatrix.x4.b16 fragments + 3-stage cp.async pipeline,
// SW128-swizzled smem. R4: CTA tile 128x128 (was 128x256) -> 96KB smem, <=128
// regs, 2 CTAs/SM co-residency to hide sync/ldsm latency.

namespace {
constexpr int Tdim = 8192;
constexpr int Idim = 512;
constexpr int Edim = 16;
constexpr int Ktok = 1024;
constexpr int Jdim = 512;

constexpr int BM = 128;            // tok tile (M)
constexpr int BN = 128;            // j tile (N)
constexpr int NKT = Idim / 32;     // 16 k-tiles (128B rows)
constexpr int NSTAGE = 3;

constexpr int A_BYTES = BM * 128;                 // 16KB
constexpr int B_BYTES = BN * 128;                 // 16KB
constexpr int STAGE_BYTES = A_BYTES + B_BYTES;    // 32KB
constexpr int SMEM_TOTAL = NSTAGE * STAGE_BYTES;  // 98304

__device__ float g_Wt[(size_t)Edim * Jdim * Idim];  // Wt[e][j][i], tf32-rounded

__device__ __forceinline__ uint32_t smem_u32(const void* p) {
    uint32_t a;
    asm("{ .reg .u64 t; cvta.to.shared.u64 t, %1; cvt.u32.u64 %0, t; }" : "=r"(a) : "l"(p));
    return a;
}
__device__ __forceinline__ uint32_t f2tf(float f) {
    uint32_t u;
    asm("cvt.rna.tf32.f32 %0, %1;" : "=r"(u) : "f"(f));
    return u;
}
__device__ __forceinline__ uint32_t cvt_r(uint32_t v) {
    uint32_t u;
    asm("cvt.rna.tf32.f32 %0, %1;" : "=r"(u) : "r"(v));
    return u;
}
__device__ __forceinline__ void cp16(uint32_t dst, const void* src) {
    asm volatile("cp.async.cg.shared.global [%0], [%1], 16;" :: "r"(dst), "l"(src) : "memory");
}
__device__ __forceinline__ void cp_commit() {
    asm volatile("cp.async.commit_group;" ::: "memory");
}
__device__ __forceinline__ void cp_wait2() {
    asm volatile("cp.async.wait_group 2;" ::: "memory");
}
__device__ __forceinline__ void ldsm4(uint32_t* r, uint32_t addr) {
    asm volatile("ldmatrix.sync.aligned.m8n8.x4.shared.b16 {%0,%1,%2,%3}, [%4];"
                 : "=r"(r[0]), "=r"(r[1]), "=r"(r[2]), "=r"(r[3]) : "r"(addr));
}
__device__ __forceinline__ void mma8(float* c, uint32_t a0, uint32_t a1, uint32_t a2,
                                     uint32_t a3, uint32_t b0, uint32_t b1) {
    asm volatile(
        "mma.sync.aligned.m16n8k8.row.col.f32.tf32.tf32.f32 "
        "{%0,%1,%2,%3}, {%4,%5,%6,%7}, {%8,%9}, {%0,%1,%2,%3};\n"
        : "+f"(c[0]), "+f"(c[1]), "+f"(c[2]), "+f"(c[3])
        : "r"(a0), "r"(a1), "r"(a2), "r"(a3), "r"(b0), "r"(b1));
}
}  // namespace

// ---- W[e][i][j] -> Wt[e][j][i], rounded to tf32 ----
__global__ void transpose_w(const float* __restrict__ W) {
    __shared__ float tile[32][33];
    const int e = blockIdx.z;
    const int i0 = blockIdx.x * 32, j0 = blockIdx.y * 32;
    const float* Wp = W + (size_t)e * Idim * Jdim;
    float* Wtp = g_Wt + (size_t)e * Jdim * Idim;
    const int tx = threadIdx.x, ty = threadIdx.y;  // (32,8)
    #pragma unroll
    for (int r = 0; r < 32; r += 8)
        tile[ty + r][tx] = Wp[(size_t)(i0 + ty + r) * Jdim + j0 + tx];
    __syncthreads();
    #pragma unroll
    for (int r = 0; r < 32; r += 8)
        Wtp[(size_t)(j0 + ty + r) * Idim + i0 + tx] =
            __uint_as_float(f2tf(tile[tx][ty + r]));
}

// ---- fused gather + GEMM ----
extern __shared__ __align__(1024) unsigned char smem_raw[];

__global__ __launch_bounds__(256, 2) void eg_mma(
    const float* __restrict__ x,     // [B, T, I]
    const int*   __restrict__ Ind,   // [B, E, K]
    float*       __restrict__ out)   // [B, E, K, J]
{
    const uint32_t sb = smem_u32(smem_raw);

    const int be   = blockIdx.z;
    const int b    = be >> 4;
    const int e    = be & 15;
    const int j0   = blockIdx.x * BN;
    const int tok0 = blockIdx.y * BM;

    const int t    = threadIdx.x;
    const int warp = t >> 5;
    const int lane = t & 31;
    const int warp_m = warp & 1;   // 2 x 64 tok
    const int warp_n = warp >> 1;  // 4 x 32 j
    const int grp = lane >> 2;
    const int tig = lane & 3;

    // ---- cp.async assignments: 16B chunks, 128B rows ----
    const int ccol = t & 7;        // 16B col within row
    const int rb   = t >> 3;       // 0..31
    const uint32_t sw16 = (uint32_t)((ccol ^ (rb & 7)) << 4);
    const uint32_t dst_row = (uint32_t)rb * 128 + sw16;

    const float* asrc[4];
    #pragma unroll
    for (int i = 0; i < 4; ++i) {
        const int tok = Ind[(size_t)be * Ktok + tok0 + rb + 32 * i];
        asrc[i] = x + ((size_t)b * Tdim + tok) * Idim + ccol * 4;
    }
    const float* bsrc = g_Wt + ((size_t)e * Jdim + j0 + rb) * Idim + ccol * 4;

    // ---- ldmatrix per-lane addressing ----
    const int l7 = lane & 7;
    const uint32_t a_lm = (uint32_t)(warp_m * 64 + ((lane >> 3) & 1) * 8 + l7) * 128;
    const uint32_t akc  = (uint32_t)(lane >> 4);        // 0/1
    const uint32_t b_lm = (uint32_t)(warp_n * 32 + ((lane >> 4) << 3) + l7) * 128;
    const uint32_t bkc  = (uint32_t)((lane >> 3) & 1);  // 0/1

    float acc[4][4][4];
    #pragma unroll
    for (int i = 0; i < 4; ++i)
        #pragma unroll
        for (int j = 0; j < 4; ++j)
            #pragma unroll
            for (int q = 0; q < 4; ++q) acc[i][j][q] = 0.0f;

    auto issue = [&](int s, int kt) {
        const uint32_t as = sb + (uint32_t)(s * STAGE_BYTES) + dst_row;
        #pragma unroll
        for (int i = 0; i < 4; ++i) cp16(as + i * 4096u, asrc[i] + kt * 32);
        const uint32_t bs = sb + (uint32_t)(s * STAGE_BYTES + A_BYTES) + dst_row;
        #pragma unroll
        for (int i = 0; i < 4; ++i) cp16(bs + i * 4096u, bsrc + kt * 32 + (size_t)i * 32 * Idim);
    };

    issue(0, 0); cp_commit();
    issue(1, 1); cp_commit();

    for (int kt = 0; kt < NKT; ++kt) {
        if (kt + 2 < NKT) issue((kt + 2) % NSTAGE, kt + 2);
        cp_commit();
        cp_wait2();
        __syncthreads();

        const int s = kt % NSTAGE;
        const uint32_t Abase = sb + (uint32_t)(s * STAGE_BYTES) + a_lm;
        const uint32_t Bbase = sb + (uint32_t)(s * STAGE_BYTES + A_BYTES) + b_lm;

        #pragma unroll
        for (int ks = 0; ks < 4; ++ks) {
            uint32_t af[4][4], bf[2][4];
            #pragma unroll
            for (int fm = 0; fm < 4; ++fm)
                ldsm4(af[fm], Abase + fm * 2048u + (((2u * ks + akc) ^ (uint32_t)l7) << 4));
            #pragma unroll
            for (int p = 0; p < 2; ++p)
                ldsm4(bf[p], Bbase + p * 2048u + (((2u * ks + bkc) ^ (uint32_t)l7) << 4));
            #pragma unroll
            for (int fm = 0; fm < 4; ++fm)
                #pragma unroll
                for (int q = 0; q < 4; ++q) af[fm][q] = cvt_r(af[fm][q]);
            #pragma unroll
            for (int fm = 0; fm < 4; ++fm)
                #pragma unroll
                for (int p = 0; p < 2; ++p) {
                    mma8(acc[fm][2 * p],     af[fm][0], af[fm][1], af[fm][2], af[fm][3],
                         bf[p][0], bf[p][1]);
                    mma8(acc[fm][2 * p + 1], af[fm][0], af[fm][1], af[fm][2], af[fm][3],
                         bf[p][2], bf[p][3]);
                }
        }
        __syncthreads();
    }

    // ---- epilogue ----
    float* ob = out + ((size_t)be * Ktok) * Jdim;
    #pragma unroll
    for (int fm = 0; fm < 4; ++fm) {
        const int r0 = tok0 + warp_m * 64 + fm * 16 + grp;
        #pragma unroll
        for (int fn = 0; fn < 4; ++fn) {
            const int cc = j0 + warp_n * 32 + fn * 8 + 2 * tig;
            *reinterpret_cast<float2*>(ob + (size_t)r0 * Jdim + cc) =
                make_float2(acc[fm][fn][0], acc[fm][fn][1]);
            *reinterpret_cast<float2*>(ob + (size_t)(r0 + 8) * Jdim + cc) =
                make_float2(acc[fm][fn][2], acc[fm][fn][3]);
        }
    }
}

extern "C" void kernel_launch(void* const* d_in, const int* in_sizes, int n_in,
                              void* d_out, int out_size) {
    const float* x   = (const float*)d_in[0];
    const int*   Ind = (const int*)d_in[1];
    const float* W   = (const float*)d_in[2];
    float*       out = (float*)d_out;

    static bool init_done = false;
    if (!init_done) {
        cudaFuncSetAttribute(eg_mma, cudaFuncAttributeMaxDynamicSharedMemorySize,
                             SMEM_TOTAL);
        init_done = true;
    }

    {
        dim3 g(Idim / 32, Jdim / 32, Edim), blk(32, 8);
        transpose_w<<<g, blk>>>(W);
    }
    {
        dim3 g(Jdim / BN, Ktok / BM, 8 * Edim);  // (4, 8, 128)
        eg_mma<<<g, 256, SMEM_TOTAL>>>(x, Ind, out);
    }
}

// round 8
// speedup vs baseline: 2.3819x; 1.1037x over previous
#include <cuda_runtime.h>
#include <cstdint>
#include <cstddef>

// ExpertGather, sm_103 baseline ISA. out[b,e,k,j] = sum_i x[b,Ind[b,e,k],i]*W[e,i,j]
// B=8 T=8192 I=512 E=16 K=1024 J=512, fp32.
//
// tf32 mma.sync.m16n8k8 + ldmatrix.x4.b16 + 3-stage cp.async, SW128 swizzle.
// R6: no in-loop cvt (x operand truncated to tf32 by HW; W pre-rounded RNA),
// single __syncthreads per k-tile (wait_group 1 before sync, issue after).

namespace {
constexpr int Tdim = 8192;
constexpr int Idim = 512;
constexpr int Edim = 16;
constexpr int Ktok = 1024;
constexpr int Jdim = 512;

constexpr int BM = 128;            // tok tile (M)
constexpr int BN = 128;            // j tile (N)
constexpr int NKT = Idim / 32;     // 16 k-tiles (128B rows)
constexpr int NSTAGE = 3;

constexpr int A_BYTES = BM * 128;                 // 16KB
constexpr int B_BYTES = BN * 128;                 // 16KB
constexpr int STAGE_BYTES = A_BYTES + B_BYTES;    // 32KB
constexpr int SMEM_TOTAL = NSTAGE * STAGE_BYTES;  // 98304

__device__ float g_Wt[(size_t)Edim * Jdim * Idim];  // Wt[e][j][i], tf32-rounded

__device__ __forceinline__ uint32_t smem_u32(const void* p) {
    uint32_t a;
    asm("{ .reg .u64 t; cvta.to.shared.u64 t, %1; cvt.u32.u64 %0, t; }" : "=r"(a) : "l"(p));
    return a;
}
__device__ __forceinline__ uint32_t f2tf(float f) {
    uint32_t u;
    asm("cvt.rna.tf32.f32 %0, %1;" : "=r"(u) : "f"(f));
    return u;
}
__device__ __forceinline__ void cp16(uint32_t dst, const void* src) {
    asm volatile("cp.async.cg.shared.global [%0], [%1], 16;" :: "r"(dst), "l"(src) : "memory");
}
__device__ __forceinline__ void cp_commit() {
    asm volatile("cp.async.commit_group;" ::: "memory");
}
__device__ __forceinline__ void cp_wait1() {
    asm volatile("cp.async.wait_group 1;" ::: "memory");
}
__device__ __forceinline__ void ldsm4(uint32_t* r, uint32_t addr) {
    asm volatile("ldmatrix.sync.aligned.m8n8.x4.shared.b16 {%0,%1,%2,%3}, [%4];"
                 : "=r"(r[0]), "=r"(r[1]), "=r"(r[2]), "=r"(r[3]) : "r"(addr));
}
__device__ __forceinline__ void mma8(float* c, uint32_t a0, uint32_t a1, uint32_t a2,
                                     uint32_t a3, uint32_t b0, uint32_t b1) {
    asm volatile(
        "mma.sync.aligned.m16n8k8.row.col.f32.tf32.tf32.f32 "
        "{%0,%1,%2,%3}, {%4,%5,%6,%7}, {%8,%9}, {%0,%1,%2,%3};\n"
        : "+f"(c[0]), "+f"(c[1]), "+f"(c[2]), "+f"(c[3])
        : "r"(a0), "r"(a1), "r"(a2), "r"(a3), "r"(b0), "r"(b1));
}
}  // namespace

// ---- W[e][i][j] -> Wt[e][j][i], rounded to tf32 (RNA) ----
__global__ void transpose_w(const float* __restrict__ W) {
    __shared__ float tile[32][33];
    const int e = blockIdx.z;
    const int i0 = blockIdx.x * 32, j0 = blockIdx.y * 32;
    const float* Wp = W + (size_t)e * Idim * Jdim;
    float* Wtp = g_Wt + (size_t)e * Jdim * Idim;
    const int tx = threadIdx.x, ty = threadIdx.y;  // (32,8)
    #pragma unroll
    for (int r = 0; r < 32; r += 8)
        tile[ty + r][tx] = Wp[(size_t)(i0 + ty + r) * Jdim + j0 + tx];
    __syncthreads();
    #pragma unroll
    for (int r = 0; r < 32; r += 8)
        Wtp[(size_t)(j0 + ty + r) * Idim + i0 + tx] =
            __uint_as_float(f2tf(tile[tx][ty + r]));
}

// ---- fused gather + GEMM ----
extern __shared__ __align__(1024) unsigned char smem_raw[];

__global__ __launch_bounds__(256, 2) void eg_mma(
    const float* __restrict__ x,     // [B, T, I]
    const int*   __restrict__ Ind,   // [B, E, K]
    float*       __restrict__ out)   // [B, E, K, J]
{
    const uint32_t sb = smem_u32(smem_raw);

    const int be   = blockIdx.z;
    const int b    = be >> 4;
    const int e    = be & 15;
    const int j0   = blockIdx.x * BN;
    const int tok0 = blockIdx.y * BM;

    const int t    = threadIdx.x;
    const int warp = t >> 5;
    const int lane = t & 31;
    const int warp_m = warp & 1;   // 2 x 64 tok
    const int warp_n = warp >> 1;  // 4 x 32 j
    const int grp = lane >> 2;
    const int tig = lane & 3;

    // ---- cp.async assignments: 16B chunks, 128B rows ----
    const int ccol = t & 7;        // 16B col within row
    const int rb   = t >> 3;       // 0..31
    const uint32_t sw16 = (uint32_t)((ccol ^ (rb & 7)) << 4);
    const uint32_t dst_row = (uint32_t)rb * 128 + sw16;

    const float* asrc[4];
    #pragma unroll
    for (int i = 0; i < 4; ++i) {
        const int tok = Ind[(size_t)be * Ktok + tok0 + rb + 32 * i];
        asrc[i] = x + ((size_t)b * Tdim + tok) * Idim + ccol * 4;
    }
    const float* bsrc = g_Wt + ((size_t)e * Jdim + j0 + rb) * Idim + ccol * 4;

    // ---- ldmatrix per-lane addressing ----
    const int l7 = lane & 7;
    const uint32_t a_lm = (uint32_t)(warp_m * 64 + ((lane >> 3) & 1) * 8 + l7) * 128;
    const uint32_t akc  = (uint32_t)(lane >> 4);        // 0/1
    const uint32_t b_lm = (uint32_t)(warp_n * 32 + ((lane >> 4) << 3) + l7) * 128;
    const uint32_t bkc  = (uint32_t)((lane >> 3) & 1);  // 0/1

    float acc[4][4][4];
    #pragma unroll
    for (int i = 0; i < 4; ++i)
        #pragma unroll
        for (int j = 0; j < 4; ++j)
            #pragma unroll
            for (int q = 0; q < 4; ++q) acc[i][j][q] = 0.0f;

    auto issue = [&](int s, int kt) {
        const uint32_t as = sb + (uint32_t)(s * STAGE_BYTES) + dst_row;
        #pragma unroll
        for (int i = 0; i < 4; ++i) cp16(as + i * 4096u, asrc[i] + kt * 32);
        const uint32_t bs = sb + (uint32_t)(s * STAGE_BYTES + A_BYTES) + dst_row;
        #pragma unroll
        for (int i = 0; i < 4; ++i) cp16(bs + i * 4096u, bsrc + kt * 32 + (size_t)i * 32 * Idim);
    };

    issue(0, 0); cp_commit();
    issue(1, 1); cp_commit();

    for (int kt = 0; kt < NKT; ++kt) {
        cp_wait1();          // stage kt%3 data resident (<=1 group pending)
        __syncthreads();     // + all warps done reading stage (kt+2)%3 (compute kt-1)
        if (kt + 2 < NKT) { issue((kt + 2) % NSTAGE, kt + 2); cp_commit(); }

        const int s = kt % NSTAGE;
        const uint32_t Abase = sb + (uint32_t)(s * STAGE_BYTES) + a_lm;
        const uint32_t Bbase = sb + (uint32_t)(s * STAGE_BYTES + A_BYTES) + b_lm;

        #pragma unroll
        for (int ks = 0; ks < 4; ++ks) {
            uint32_t af[4][4], bf[2][4];
            #pragma unroll
            for (int fm = 0; fm < 4; ++fm)
                ldsm4(af[fm], Abase + fm * 2048u + (((2u * ks + akc) ^ (uint32_t)l7) << 4));
            #pragma unroll
            for (int p = 0; p < 2; ++p)
                ldsm4(bf[p], Bbase + p * 2048u + (((2u * ks + bkc) ^ (uint32_t)l7) << 4));
            // no cvt: HW reads tf32 MSBs of raw fp32 A; B pre-rounded RNA.
            #pragma unroll
            for (int fm = 0; fm < 4; ++fm)
                #pragma unroll
                for (int p = 0; p < 2; ++p) {
                    mma8(acc[fm][2 * p],     af[fm][0], af[fm][1], af[fm][2], af[fm][3],
                         bf[p][0], bf[p][1]);
                    mma8(acc[fm][2 * p + 1], af[fm][0], af[fm][1], af[fm][2], af[fm][3],
                         bf[p][2], bf[p][3]);
                }
        }
    }

    // ---- epilogue ----
    float* ob = out + ((size_t)be * Ktok) * Jdim;
    #pragma unroll
    for (int fm = 0; fm < 4; ++fm) {
        const int r0 = tok0 + warp_m * 64 + fm * 16 + grp;
        #pragma unroll
        for (int fn = 0; fn < 4; ++fn) {
            const int cc = j0 + warp_n * 32 + fn * 8 + 2 * tig;
            *reinterpret_cast<float2*>(ob + (size_t)r0 * Jdim + cc) =
                make_float2(acc[fm][fn][0], acc[fm][fn][1]);
            *reinterpret_cast<float2*>(ob + (size_t)(r0 + 8) * Jdim + cc) =
                make_float2(acc[fm][fn][2], acc[fm][fn][3]);
        }
    }
}

extern "C" void kernel_launch(void* const* d_in, const int* in_sizes, int n_in,
                              void* d_out, int out_size) {
    const float* x   = (const float*)d_in[0];
    const int*   Ind = (const int*)d_in[1];
    const float* W   = (const float*)d_in[2];
    float*       out = (float*)d_out;

    static bool init_done = false;
    if (!init_done) {
        cudaFuncSetAttribute(eg_mma, cudaFuncAttributeMaxDynamicSharedMemorySize,
                             SMEM_TOTAL);
        init_done = true;
    }

    {
        dim3 g(Idim / 32, Jdim / 32, Edim), blk(32, 8);
        transpose_w<<<g, blk>>>(W);
    }
    {
        dim3 g(Jdim / BN, Ktok / BM, 8 * Edim);  // (4, 8, 128)
        eg_mma<<<g, 256, SMEM_TOTAL>>>(x, Ind, out);
    }
}

// round 9
// speedup vs baseline: 2.4017x; 1.0083x over previous
#include <cuda_runtime.h>
#include <cstdint>
#include <cstddef>

// ExpertGather, sm_103 baseline ISA. out[b,e,k,j] = sum_i x[b,Ind[b,e,k],i]*W[e,i,j]
// B=8 T=8192 I=512 E=16 K=1024 J=512, fp32.
//
// tf32 mma.sync.m16n8k8 + ldmatrix.x4.b16 + 3-stage cp.async, SW128 swizzle.
// R9: warp tile 64x64 (4 warps, 128 threads, CTA 128x128) -> smem crossbar
// bytes/FLOP down 1.5x (crossbar is the measured binder). 2 CTAs/SM.

namespace {
constexpr int Tdim = 8192;
constexpr int Idim = 512;
constexpr int Edim = 16;
constexpr int Ktok = 1024;
constexpr int Jdim = 512;

constexpr int BM = 128;            // tok tile (M)
constexpr int BN = 128;            // j tile (N)
constexpr int NKT = Idim / 32;     // 16 k-tiles (128B rows)
constexpr int NSTAGE = 3;
constexpr int THREADS = 128;

constexpr int A_BYTES = BM * 128;                 // 16KB
constexpr int B_BYTES = BN * 128;                 // 16KB
constexpr int STAGE_BYTES = A_BYTES + B_BYTES;    // 32KB
constexpr int SMEM_TOTAL = NSTAGE * STAGE_BYTES;  // 98304

__device__ float g_Wt[(size_t)Edim * Jdim * Idim];  // Wt[e][j][i], tf32-rounded

__device__ __forceinline__ uint32_t smem_u32(const void* p) {
    uint32_t a;
    asm("{ .reg .u64 t; cvta.to.shared.u64 t, %1; cvt.u32.u64 %0, t; }" : "=r"(a) : "l"(p));
    return a;
}
__device__ __forceinline__ uint32_t f2tf(float f) {
    uint32_t u;
    asm("cvt.rna.tf32.f32 %0, %1;" : "=r"(u) : "f"(f));
    return u;
}
__device__ __forceinline__ void cp16(uint32_t dst, const void* src) {
    asm volatile("cp.async.cg.shared.global [%0], [%1], 16;" :: "r"(dst), "l"(src) : "memory");
}
__device__ __forceinline__ void cp_commit() {
    asm volatile("cp.async.commit_group;" ::: "memory");
}
__device__ __forceinline__ void cp_wait1() {
    asm volatile("cp.async.wait_group 1;" ::: "memory");
}
__device__ __forceinline__ void ldsm4(uint32_t* r, uint32_t addr) {
    asm volatile("ldmatrix.sync.aligned.m8n8.x4.shared.b16 {%0,%1,%2,%3}, [%4];"
                 : "=r"(r[0]), "=r"(r[1]), "=r"(r[2]), "=r"(r[3]) : "r"(addr));
}
__device__ __forceinline__ void mma8(float* c, const uint32_t* a, uint32_t b0, uint32_t b1) {
    asm volatile(
        "mma.sync.aligned.m16n8k8.row.col.f32.tf32.tf32.f32 "
        "{%0,%1,%2,%3}, {%4,%5,%6,%7}, {%8,%9}, {%0,%1,%2,%3};\n"
        : "+f"(c[0]), "+f"(c[1]), "+f"(c[2]), "+f"(c[3])
        : "r"(a[0]), "r"(a[1]), "r"(a[2]), "r"(a[3]), "r"(b0), "r"(b1));
}
}  // namespace

// ---- W[e][i][j] -> Wt[e][j][i], rounded to tf32 (RNA) ----
__global__ void transpose_w(const float* __restrict__ W) {
    __shared__ float tile[32][33];
    const int e = blockIdx.z;
    const int i0 = blockIdx.x * 32, j0 = blockIdx.y * 32;
    const float* Wp = W + (size_t)e * Idim * Jdim;
    float* Wtp = g_Wt + (size_t)e * Jdim * Idim;
    const int tx = threadIdx.x, ty = threadIdx.y;  // (32,8)
    #pragma unroll
    for (int r = 0; r < 32; r += 8)
        tile[ty + r][tx] = Wp[(size_t)(i0 + ty + r) * Jdim + j0 + tx];
    __syncthreads();
    #pragma unroll
    for (int r = 0; r < 32; r += 8)
        Wtp[(size_t)(j0 + ty + r) * Idim + i0 + tx] =
            __uint_as_float(f2tf(tile[tx][ty + r]));
}

// ---- fused gather + GEMM ----
extern __shared__ __align__(1024) unsigned char smem_raw[];

__global__ __launch_bounds__(THREADS, 2) void eg_mma(
    const float* __restrict__ x,     // [B, T, I]
    const int*   __restrict__ Ind,   // [B, E, K]
    float*       __restrict__ out)   // [B, E, K, J]
{
    const uint32_t sb = smem_u32(smem_raw);

    const int be   = blockIdx.z;
    const int b    = be >> 4;
    const int e    = be & 15;
    const int j0   = blockIdx.x * BN;
    const int tok0 = blockIdx.y * BM;

    const int t    = threadIdx.x;
    const int warp = t >> 5;
    const int lane = t & 31;
    const int warp_m = warp & 1;   // 2 x 64 tok
    const int warp_n = warp >> 1;  // 2 x 64 j
    const int grp = lane >> 2;
    const int tig = lane & 3;

    // ---- cp.async assignments: 16B chunks, 128B rows, 128 threads ----
    const int ccol = t & 7;        // 16B col within row
    const int rb   = t >> 3;       // 0..15
    const uint32_t sw16 = (uint32_t)((ccol ^ (rb & 7)) << 4);
    const uint32_t dst_row = (uint32_t)rb * 128 + sw16;

    // A rows rb + 16*i (i=0..7): gathered; store 32-bit byte offsets
    const float* xb = x + (size_t)b * Tdim * Idim;
    uint32_t aoff[8];
    #pragma unroll
    for (int i = 0; i < 8; ++i) {
        const int tok = Ind[(size_t)be * Ktok + tok0 + rb + 16 * i];
        aoff[i] = (uint32_t)tok * (Idim * 4) + (uint32_t)ccol * 16;
    }
    const float* bsrc = g_Wt + ((size_t)e * Jdim + j0 + rb) * Idim + ccol * 4;

    // ---- ldmatrix per-lane addressing ----
    const int l7 = lane & 7;
    const uint32_t a_lm = (uint32_t)(warp_m * 64 + ((lane >> 3) & 1) * 8 + l7) * 128;
    const uint32_t akc  = (uint32_t)(lane >> 4);        // 0/1
    const uint32_t b_lm = (uint32_t)(warp_n * 64 + ((lane >> 4) << 3) + l7) * 128;
    const uint32_t bkc  = (uint32_t)((lane >> 3) & 1);  // 0/1

    float acc[4][8][4];
    #pragma unroll
    for (int i = 0; i < 4; ++i)
        #pragma unroll
        for (int j = 0; j < 8; ++j)
            #pragma unroll
            for (int q = 0; q < 4; ++q) acc[i][j][q] = 0.0f;

    auto issue = [&](int s, int kt) {
        const uint32_t as = sb + (uint32_t)(s * STAGE_BYTES) + dst_row;
        const char* xkb = (const char*)(xb + kt * 32);
        #pragma unroll
        for (int i = 0; i < 8; ++i) cp16(as + i * 2048u, xkb + aoff[i]);
        const uint32_t bs = sb + (uint32_t)(s * STAGE_BYTES + A_BYTES) + dst_row;
        #pragma unroll
        for (int i = 0; i < 8; ++i) cp16(bs + i * 2048u, bsrc + kt * 32 + (size_t)(16 * i) * Idim);
    };

    issue(0, 0); cp_commit();
    issue(1, 1); cp_commit();

    for (int kt = 0; kt < NKT; ++kt) {
        cp_wait1();          // stage kt%3 resident (<=1 group pending)
        __syncthreads();     // all warps done reading stage (kt+2)%3
        if (kt + 2 < NKT) { issue((kt + 2) % NSTAGE, kt + 2); cp_commit(); }

        const int s = kt % NSTAGE;
        const uint32_t Abase = sb + (uint32_t)(s * STAGE_BYTES) + a_lm;
        const uint32_t Bbase = sb + (uint32_t)(s * STAGE_BYTES + A_BYTES) + b_lm;

        #pragma unroll
        for (int ks = 0; ks < 4; ++ks) {
            uint32_t af[4][4], bf[4][4];
            #pragma unroll
            for (int fm = 0; fm < 4; ++fm)
                ldsm4(af[fm], Abase + fm * 2048u + (((2u * ks + akc) ^ (uint32_t)l7) << 4));
            #pragma unroll
            for (int p = 0; p < 4; ++p)
                ldsm4(bf[p], Bbase + p * 2048u + (((2u * ks + bkc) ^ (uint32_t)l7) << 4));
            // no cvt: HW truncates A to tf32; B (Wt) pre-rounded RNA.
            #pragma unroll
            for (int fm = 0; fm < 4; ++fm)
                #pragma unroll
                for (int p = 0; p < 4; ++p) {
                    mma8(acc[fm][2 * p],     af[fm], bf[p][0], bf[p][1]);
                    mma8(acc[fm][2 * p + 1], af[fm], bf[p][2], bf[p][3]);
                }
        }
    }

    // ---- epilogue ----
    float* ob = out + ((size_t)be * Ktok) * Jdim;
    #pragma unroll
    for (int fm = 0; fm < 4; ++fm) {
        const int r0 = tok0 + warp_m * 64 + fm * 16 + grp;
        #pragma unroll
        for (int fn = 0; fn < 8; ++fn) {
            const int cc = j0 + warp_n * 64 + fn * 8 + 2 * tig;
            *reinterpret_cast<float2*>(ob + (size_t)r0 * Jdim + cc) =
                make_float2(acc[fm][fn][0], acc[fm][fn][1]);
            *reinterpret_cast<float2*>(ob + (size_t)(r0 + 8) * Jdim + cc) =
                make_float2(acc[fm][fn][2], acc[fm][fn][3]);
        }
    }
}

extern "C" void kernel_launch(void* const* d_in, const int* in_sizes, int n_in,
                              void* d_out, int out_size) {
    const float* x   = (const float*)d_in[0];
    const int*   Ind = (const int*)d_in[1];
    const float* W   = (const float*)d_in[2];
    float*       out = (float*)d_out;

    static bool init_done = false;
    if (!init_done) {
        cudaFuncSetAttribute(eg_mma, cudaFuncAttributeMaxDynamicSharedMemorySize,
                             SMEM_TOTAL);
        init_done = true;
    }

    {
        dim3 g(Idim / 32, Jdim / 32, Edim), blk(32, 8);
        transpose_w<<<g, blk>>>(W);
    }
    {
        dim3 g(Jdim / BN, Ktok / BM, 8 * Edim);  // (4, 8, 128)
        eg_mma<<<g, THREADS, SMEM_TOTAL>>>(x, Ind, out);
    }
}

// round 10
// speedup vs baseline: 2.6181x; 1.0901x over previous
#include <cuda_runtime.h>
#include <cstdint>
#include <cstddef>

// ExpertGather, sm_103 baseline ISA. out[b,e,k,j] = sum_i x[b,Ind[b,e,k],i]*W[e,i,j]
// B=8 T=8192 I=512 E=16 K=1024 J=512, fp32.
//
// tf32 mma.sync.m16n8k8 + ldmatrix.x4.b16 + 3-stage cp.async, SW128 swizzle.
// R10: explicit ks software pipeline — double-buffered fragments (load ks+1
// during mma of ks), fragment loads hoisted above cp.async issue burst.
// Warp tile 64x64, 4 warps, CTA 128x128, 2 CTAs/SM.

namespace {
constexpr int Tdim = 8192;
constexpr int Idim = 512;
constexpr int Edim = 16;
constexpr int Ktok = 1024;
constexpr int Jdim = 512;

constexpr int BM = 128;            // tok tile (M)
constexpr int BN = 128;            // j tile (N)
constexpr int NKT = Idim / 32;     // 16 k-tiles (128B rows)
constexpr int NSTAGE = 3;
constexpr int THREADS = 128;

constexpr int A_BYTES = BM * 128;                 // 16KB
constexpr int B_BYTES = BN * 128;                 // 16KB
constexpr int STAGE_BYTES = A_BYTES + B_BYTES;    // 32KB
constexpr int SMEM_TOTAL = NSTAGE * STAGE_BYTES;  // 98304

__device__ float g_Wt[(size_t)Edim * Jdim * Idim];  // Wt[e][j][i], tf32-rounded

__device__ __forceinline__ uint32_t smem_u32(const void* p) {
    uint32_t a;
    asm("{ .reg .u64 t; cvta.to.shared.u64 t, %1; cvt.u32.u64 %0, t; }" : "=r"(a) : "l"(p));
    return a;
}
__device__ __forceinline__ uint32_t f2tf(float f) {
    uint32_t u;
    asm("cvt.rna.tf32.f32 %0, %1;" : "=r"(u) : "f"(f));
    return u;
}
__device__ __forceinline__ void cp16(uint32_t dst, const void* src) {
    asm volatile("cp.async.cg.shared.global [%0], [%1], 16;" :: "r"(dst), "l"(src) : "memory");
}
__device__ __forceinline__ void cp_commit() {
    asm volatile("cp.async.commit_group;" ::: "memory");
}
__device__ __forceinline__ void cp_wait1() {
    asm volatile("cp.async.wait_group 1;" ::: "memory");
}
__device__ __forceinline__ void ldsm4(uint32_t* r, uint32_t addr) {
    asm volatile("ldmatrix.sync.aligned.m8n8.x4.shared.b16 {%0,%1,%2,%3}, [%4];"
                 : "=r"(r[0]), "=r"(r[1]), "=r"(r[2]), "=r"(r[3]) : "r"(addr));
}
__device__ __forceinline__ void mma8(float* c, const uint32_t* a, uint32_t b0, uint32_t b1) {
    asm volatile(
        "mma.sync.aligned.m16n8k8.row.col.f32.tf32.tf32.f32 "
        "{%0,%1,%2,%3}, {%4,%5,%6,%7}, {%8,%9}, {%0,%1,%2,%3};\n"
        : "+f"(c[0]), "+f"(c[1]), "+f"(c[2]), "+f"(c[3])
        : "r"(a[0]), "r"(a[1]), "r"(a[2]), "r"(a[3]), "r"(b0), "r"(b1));
}
}  // namespace

// ---- W[e][i][j] -> Wt[e][j][i], rounded to tf32 (RNA) ----
__global__ void transpose_w(const float* __restrict__ W) {
    __shared__ float tile[32][33];
    const int e = blockIdx.z;
    const int i0 = blockIdx.x * 32, j0 = blockIdx.y * 32;
    const float* Wp = W + (size_t)e * Idim * Jdim;
    float* Wtp = g_Wt + (size_t)e * Jdim * Idim;
    const int tx = threadIdx.x, ty = threadIdx.y;  // (32,8)
    #pragma unroll
    for (int r = 0; r < 32; r += 8)
        tile[ty + r][tx] = Wp[(size_t)(i0 + ty + r) * Jdim + j0 + tx];
    __syncthreads();
    #pragma unroll
    for (int r = 0; r < 32; r += 8)
        Wtp[(size_t)(j0 + ty + r) * Idim + i0 + tx] =
            __uint_as_float(f2tf(tile[tx][ty + r]));
}

// ---- fused gather + GEMM ----
extern __shared__ __align__(1024) unsigned char smem_raw[];

__global__ __launch_bounds__(THREADS, 2) void eg_mma(
    const float* __restrict__ x,     // [B, T, I]
    const int*   __restrict__ Ind,   // [B, E, K]
    float*       __restrict__ out)   // [B, E, K, J]
{
    const uint32_t sb = smem_u32(smem_raw);

    const int be   = blockIdx.z;
    const int b    = be >> 4;
    const int e    = be & 15;
    const int j0   = blockIdx.x * BN;
    const int tok0 = blockIdx.y * BM;

    const int t    = threadIdx.x;
    const int warp = t >> 5;
    const int lane = t & 31;
    const int warp_m = warp & 1;   // 2 x 64 tok
    const int warp_n = warp >> 1;  // 2 x 64 j
    const int grp = lane >> 2;
    const int tig = lane & 3;

    // ---- cp.async assignments: 16B chunks, 128B rows, 128 threads ----
    const int ccol = t & 7;        // 16B col within row
    const int rb   = t >> 3;       // 0..15
    const uint32_t sw16 = (uint32_t)((ccol ^ (rb & 7)) << 4);
    const uint32_t dst_row = (uint32_t)rb * 128 + sw16;

    // A rows rb + 16*i (i=0..7): gathered; 32-bit byte offsets
    const float* xb = x + (size_t)b * Tdim * Idim;
    uint32_t aoff[8];
    #pragma unroll
    for (int i = 0; i < 8; ++i) {
        const int tok = Ind[(size_t)be * Ktok + tok0 + rb + 16 * i];
        aoff[i] = (uint32_t)tok * (Idim * 4) + (uint32_t)ccol * 16;
    }
    const float* bsrc = g_Wt + ((size_t)e * Jdim + j0 + rb) * Idim + ccol * 4;

    // ---- ldmatrix per-lane addressing ----
    const int l7 = lane & 7;
    const uint32_t a_lm = (uint32_t)(warp_m * 64 + ((lane >> 3) & 1) * 8 + l7) * 128;
    const uint32_t akc  = (uint32_t)(lane >> 4);        // 0/1
    const uint32_t b_lm = (uint32_t)(warp_n * 64 + ((lane >> 4) << 3) + l7) * 128;
    const uint32_t bkc  = (uint32_t)((lane >> 3) & 1);  // 0/1

    float acc[4][8][4];
    #pragma unroll
    for (int i = 0; i < 4; ++i)
        #pragma unroll
        for (int j = 0; j < 8; ++j)
            #pragma unroll
            for (int q = 0; q < 4; ++q) acc[i][j][q] = 0.0f;

    auto issue = [&](int s, int kt) {
        const uint32_t as = sb + (uint32_t)(s * STAGE_BYTES) + dst_row;
        const char* xkb = (const char*)(xb + kt * 32);
        #pragma unroll
        for (int i = 0; i < 8; ++i) cp16(as + i * 2048u, xkb + aoff[i]);
        const uint32_t bs = sb + (uint32_t)(s * STAGE_BYTES + A_BYTES) + dst_row;
        #pragma unroll
        for (int i = 0; i < 8; ++i) cp16(bs + i * 2048u, bsrc + kt * 32 + (size_t)(16 * i) * Idim);
    };

    issue(0, 0); cp_commit();
    issue(1, 1); cp_commit();

    uint32_t af[2][4][4], bf[2][4][4];

    for (int kt = 0; kt < NKT; ++kt) {
        cp_wait1();          // stage kt%3 resident (<=1 group pending)
        __syncthreads();     // all warps done reading stage (kt+2)%3

        const int s = kt % NSTAGE;
        const uint32_t Abase = sb + (uint32_t)(s * STAGE_BYTES) + a_lm;
        const uint32_t Bbase = sb + (uint32_t)(s * STAGE_BYTES + A_BYTES) + b_lm;

        // Prologue: fragments for ks=0 FIRST (critical path), then cp.async.
        #pragma unroll
        for (int fm = 0; fm < 4; ++fm)
            ldsm4(af[0][fm], Abase + fm * 2048u + ((akc ^ (uint32_t)l7) << 4));
        #pragma unroll
        for (int p = 0; p < 4; ++p)
            ldsm4(bf[0][p], Bbase + p * 2048u + ((bkc ^ (uint32_t)l7) << 4));

        if (kt + 2 < NKT) { issue((kt + 2) % NSTAGE, kt + 2); cp_commit(); }

        #pragma unroll
        for (int ks = 0; ks < 4; ++ks) {
            const int cur = ks & 1, nxt = cur ^ 1;
            if (ks < 3) {
                #pragma unroll
                for (int fm = 0; fm < 4; ++fm)
                    ldsm4(af[nxt][fm],
                          Abase + fm * 2048u + (((2u * (ks + 1) + akc) ^ (uint32_t)l7) << 4));
                #pragma unroll
                for (int p = 0; p < 4; ++p)
                    ldsm4(bf[nxt][p],
                          Bbase + p * 2048u + (((2u * (ks + 1) + bkc) ^ (uint32_t)l7) << 4));
            }
            // no cvt: HW truncates A to tf32; B (Wt) pre-rounded RNA.
            #pragma unroll
            for (int fm = 0; fm < 4; ++fm)
                #pragma unroll
                for (int p = 0; p < 4; ++p) {
                    mma8(acc[fm][2 * p],     af[cur][fm], bf[cur][p][0], bf[cur][p][1]);
                    mma8(acc[fm][2 * p + 1], af[cur][fm], bf[cur][p][2], bf[cur][p][3]);
                }
        }
    }

    // ---- epilogue ----
    float* ob = out + ((size_t)be * Ktok) * Jdim;
    #pragma unroll
    for (int fm = 0; fm < 4; ++fm) {
        const int r0 = tok0 + warp_m * 64 + fm * 16 + grp;
        #pragma unroll
        for (int fn = 0; fn < 8; ++fn) {
            const int cc = j0 + warp_n * 64 + fn * 8 + 2 * tig;
            *reinterpret_cast<float2*>(ob + (size_t)r0 * Jdim + cc) =
                make_float2(acc[fm][fn][0], acc[fm][fn][1]);
            *reinterpret_cast<float2*>(ob + (size_t)(r0 + 8) * Jdim + cc) =
                make_float2(acc[fm][fn][2], acc[fm][fn][3]);
        }
    }
}

extern "C" void kernel_launch(void* const* d_in, const int* in_sizes, int n_in,
                              void* d_out, int out_size) {
    const float* x   = (const float*)d_in[0];
    const int*   Ind = (const int*)d_in[1];
    const float* W   = (const float*)d_in[2];
    float*       out = (float*)d_out;

    static bool init_done = false;
    if (!init_done) {
        cudaFuncSetAttribute(eg_mma, cudaFuncAttributeMaxDynamicSharedMemorySize,
                             SMEM_TOTAL);
        init_done = true;
    }

    {
        dim3 g(Idim / 32, Jdim / 32, Edim), blk(32, 8);
        transpose_w<<<g, blk>>>(W);
    }
    {
        dim3 g(Jdim / BN, Ktok / BM, 8 * Edim);  // (4, 8, 128)
        eg_mma<<<g, THREADS, SMEM_TOTAL>>>(x, Ind, out);
    }
}